// round 8
// baseline (speedup 1.0000x reference)
#include <cuda_runtime.h>
#include <cuda_fp16.h>
#include <math.h>

// Fixed problem shapes: b=8, n=4096, c=32, g=4, rad=4, rank=2, k=128, in=1024, OUT=1024
#define BB    8
#define CC    32
#define GG    4
#define RADR  4
#define KK    128
#define PPC   12          // 4 neighbor + 4 sampled + 4 range-restricted
#define NP    384         // CC * PPC points per (b,k) tile
#define INSZ  1024
#define OUTSZ 1024
#define NWARP 12          // NP/32
#define HSZ   512         // dup-hash slots (384 keys @ 75% load, ~2 probes)
#define ESTRIDE 386       // halves per e-cache column (pad: conflict-free STS.32/LDS.16)

// sqrt(0.5 * log2(e)) — folds the -0.5 and exp->exp2 into the inverse sigmas.
#define SQRT_HALF_LOG2E 0.8493218383f

__device__ __forceinline__ float ex2_approx(float v) {
    float r;
    asm("ex2.approx.f32 %0, %1;" : "=f"(r) : "f"(v));
    return r;
}

__global__ __launch_bounds__(NP) void sparse_layer_kernel(
    const float* __restrict__ x,        // (8, 1024)
    const float* __restrict__ means,    // (8, 4096, 2)
    const float* __restrict__ sigmas,   // (8, 4096, 2)
    const float* __restrict__ values,   // (8, 4096)
    const float* __restrict__ su,       // (8, 128, 32, 4, 2)
    const float* __restrict__ ru,       // (8, 128, 32, 4, 2)
    float* __restrict__ out)            // (8, 1024)
{
    __shared__ float  sm0[CC], sm1[CC];
    __shared__ float4 scell[CC];            // (v0, v1, m0*v0, m1*v1)
    __shared__ float  sval[CC], svalw[CC];
    __shared__ float2 spts[NP];             // (p0 or 1e30 if dup, p1)
    __shared__ float  spart[NWARP * CC];
    __shared__ unsigned int tab[HSZ];       // hash: (id<<9)|minidx, EMPTY=~0
    __shared__ __half eh[CC * ESTRIDE];     // density cache, column-major [cell][point]

    const int bk = blockIdx.x;              // b*128 + k
    const int b  = bk >> 7;
    const int t  = threadIdx.x;
    const int w  = t >> 5;
    const int l  = t & 31;

    // ---- init hash + load per-cell params ----
    #pragma unroll
    for (int i = t; i < HSZ; i += NP) tab[i] = 0xFFFFFFFFu;
    if (t < CC) {
        int base = (bk * CC + t) * 2;
        float m0 = means[base], m1 = means[base + 1];
        float v0 = sqrtf(1.0f / (1e-6f + sigmas[base]))     * SQRT_HALF_LOG2E;
        float v1 = sqrtf(1.0f / (1e-6f + sigmas[base + 1])) * SQRT_HALF_LOG2E;
        sm0[t] = m0;
        sm1[t] = m1;
        scell[t] = make_float4(v0, v1, m0 * v0, m1 * v1);
        sval[t] = values[bk * CC + t];
    }
    __syncthreads();

    // ---- generate integer tuple for this thread's point: cell c = t/12, slot j ----
    int id;
    {
        const int c = t / PPC;
        const int j = t - c * PPC;
        const float m0v = sm0[c], m1v = sm1[c];
        const float SCL = 1.0f - 1e-6f;
        int i0, i1;
        if (j < 4) {
            // fm order (itertools.product([T,F],2)): True->floor
            i0 = (j & 2) ? (int)ceilf(m0v) : (int)floorf(m0v);
            i1 = (j & 1) ? (int)ceilf(m1v) : (int)floorf(m1v);
        } else if (j < 8) {
            int idx = ((bk * CC + c) * GG + (j - 4)) * 2;
            i0 = (int)floorf(__fmul_rn(__fmul_rn(su[idx],     SCL), 1024.0f));
            i1 = (int)floorf(__fmul_rn(__fmul_rn(su[idx + 1], SCL), 1024.0f));
        } else {
            int idx = ((bk * CC + c) * RADR + (j - 8)) * 2;
            float mn0 = rintf(m0v), mn1 = rintf(m1v);   // round half-even (jnp.round)
            float lo0 = mn0 - 8.0f, lo1 = mn1 - 8.0f;
            if (lo0 < 0.0f) lo0 = 0.0f;
            if (mn0 + 8.0f > 1024.0f) lo0 = 1008.0f;
            if (lo1 < 0.0f) lo1 = 0.0f;
            if (mn1 + 8.0f > 1024.0f) lo1 = 1008.0f;
            i0 = (int)floorf(__fadd_rn(__fmul_rn(__fmul_rn(ru[idx],     SCL), 16.0f), lo0));
            i1 = (int)floorf(__fadd_rn(__fmul_rn(__fmul_rn(ru[idx + 1], SCL), 16.0f), lo1));
        }
        id = (i0 << 10) | i1;
    }

    // ---- duplicate marking via shared hash (min thread index wins) ----
    bool dup;
    {
        const unsigned int uid = (unsigned int)id;
        const unsigned int val = (uid << 9) | (unsigned int)t;   // 20+9 bits
        unsigned int h = (uid * 2654435761u) >> 23;              // top 9 bits
        int slot;
        for (;;) {
            unsigned int old = atomicCAS(&tab[h], 0xFFFFFFFFu, val);
            if (old == 0xFFFFFFFFu) { slot = h; break; }
            if ((old >> 9) == uid)  { atomicMin(&tab[h], val); slot = h; break; }
            h = (h + 1) & (HSZ - 1);
        }
        __syncthreads();
        dup = ((tab[slot] & 511u) != (unsigned int)t);
        // dup -> p0 = 1e30 => ex2 arg -> -inf => density exactly 0
        spts[t] = make_float2(dup ? 1e30f : (float)(id >> 10), (float)(id & 1023));
    }
    __syncthreads();

    // ---- pass 1: warp w owns its 32 points, lane = cell. Colsum + fp16 e-cache ----
    {
        const float4 cp = scell[l];
        __half2* ecol = (__half2*)(eh + l * ESTRIDE);   // column l, half2-indexed
        float c0 = 0.0f, c1 = 0.0f;
        #pragma unroll
        for (int ii = 0; ii < 32; ii += 2) {
            float2 pa = spts[(w << 5) + ii];
            float2 pb = spts[(w << 5) + ii + 1];
            float a0 = __fmaf_rn(pa.x, cp.x, -cp.z);
            float a1 = __fmaf_rn(pa.y, cp.y, -cp.w);
            float b0 = __fmaf_rn(pb.x, cp.x, -cp.z);
            float b1 = __fmaf_rn(pb.y, cp.y, -cp.w);
            float ea = ex2_approx(__fmaf_rn(-a1, a1, __fmul_rn(-a0, a0)));
            float eb = ex2_approx(__fmaf_rn(-b1, b1, __fmul_rn(-b0, b0)));
            c0 += ea;
            c1 += eb;
            ecol[((w << 5) + ii) >> 1] = __floats2half2_rn(ea, eb);  // STS.32, conflict-free
        }
        spart[w * CC + l] = c0 + c1;
    }
    __syncthreads();

    // ---- column totals -> value/colsum weights ----
    if (t < CC) {
        float s = 0.0f;
        #pragma unroll
        for (int ww = 0; ww < NWARP; ++ww) s += spart[ww * CC + t];
        svalw[t] = sval[t] / s;
    }
    __syncthreads();

    // ---- pass 2: thread t owns point t; dot(e-row, svalw) from the cache ----
    {
        float a0 = 0.0f, a1 = 0.0f;
        const float2* swv = (const float2*)svalw;
        #pragma unroll
        for (int c = 0; c < CC; c += 2) {
            float2 sw = swv[c >> 1];                    // LDS.64
            float ea = __half2float(eh[c * ESTRIDE + t]);        // LDS.16 (bank-clean)
            float ebv = __half2float(eh[(c + 1) * ESTRIDE + t]);
            a0 = __fmaf_rn(ea,  sw.x, a0);
            a1 = __fmaf_rn(ebv, sw.y, a1);
        }
        if (!dup) {
            float contrib = (a0 + a1) * x[b * INSZ + (id & 1023)];
            atomicAdd(&out[b * OUTSZ + ((id >> 10) & 1023)], contrib);
        }
    }
}

extern "C" void kernel_launch(void* const* d_in, const int* in_sizes, int n_in,
                              void* d_out, int out_size)
{
    const float* x      = (const float*)d_in[0];
    const float* means  = (const float*)d_in[1];
    const float* sigmas = (const float*)d_in[2];
    const float* values = (const float*)d_in[3];
    const float* su     = (const float*)d_in[4];
    const float* ru     = (const float*)d_in[5];
    float* out = (float*)d_out;

    cudaMemsetAsync(out, 0, (size_t)out_size * sizeof(float));
    sparse_layer_kernel<<<BB * KK, NP>>>(x, means, sigmas, values, su, ru, out);
}

// round 9
// speedup vs baseline: 1.2960x; 1.2960x over previous
#include <cuda_runtime.h>
#include <math.h>

// Fixed problem shapes: b=8, n=4096, c=32, g=4, rad=4, rank=2, k=128, in=1024, OUT=1024
#define BB    8
#define CC    32
#define GG    4
#define RADR  4
#define KK    128
#define PPC   12          // 4 neighbor + 4 sampled + 4 range-restricted
#define NP    384         // CC * PPC points per (b,k) tile
#define INSZ  1024
#define OUTSZ 1024
#define NWARP 12          // NP/32
#define HSZ   512         // dup-hash slots
#define NTILES 1024
#define GRID  740         // 148 SMs x 5 resident blocks = one wave
#define NDBL  (NTILES - GRID)   // 284 blocks run a second tile

// sqrt(0.5 * log2(e)) — folds the -0.5 and exp->exp2 into the inverse sigmas.
#define SQRT_HALF_LOG2E 0.8493218383f

typedef unsigned long long ull;

__device__ __forceinline__ float ex2_approx(float v) {
    float r;
    asm("ex2.approx.f32 %0, %1;" : "=f"(r) : "f"(v));
    return r;
}
__device__ __forceinline__ ull pk2(float lo, float hi) {
    ull r; asm("mov.b64 %0, {%1, %2};" : "=l"(r) : "f"(lo), "f"(hi)); return r;
}
__device__ __forceinline__ void upk2(ull v, float& lo, float& hi) {
    asm("mov.b64 {%0, %1}, %2;" : "=f"(lo), "=f"(hi) : "l"(v));
}
__device__ __forceinline__ ull fma2(ull a, ull b, ull c) {
    ull r; asm("fma.rn.f32x2 %0, %1, %2, %3;" : "=l"(r) : "l"(a), "l"(b), "l"(c)); return r;
}
__device__ __forceinline__ ull mul2(ull a, ull b) {
    ull r; asm("mul.rn.f32x2 %0, %1, %2;" : "=l"(r) : "l"(a), "l"(b)); return r;
}

__global__ __launch_bounds__(NP) void sparse_layer_kernel(
    const float* __restrict__ x,        // (8, 1024)
    const float* __restrict__ means,    // (8, 4096, 2)
    const float* __restrict__ sigmas,   // (8, 4096, 2)
    const float* __restrict__ values,   // (8, 4096)
    const float* __restrict__ su,       // (8, 128, 32, 4, 2)
    const float* __restrict__ ru,       // (8, 128, 32, 4, 2)
    float* __restrict__ out)            // (8, 1024)
{
    __shared__ float      sm0[CC], sm1[CC];
    __shared__ ulonglong2 scell[CC];        // .x = (v0,v1) packed, .y = (-m0*v0,-m1*v1)
    __shared__ float      sval[CC], svalw[CC];
    __shared__ ull        spts[NP];         // (p0 or 1e30 if dup, p1) packed f32x2
    __shared__ float      spart[NWARP * CC];
    __shared__ unsigned int tab[HSZ];       // hash: (id<<9)|minidx, EMPTY=~0

    const int bid = blockIdx.x;
    const int t  = threadIdx.x;
    const int w  = t >> 5;
    const int l  = t & 31;
    const int ntiles = (bid < NDBL) ? 2 : 1;

    #pragma unroll 1
    for (int tt = 0; tt < ntiles; ++tt) {
        const int bk = bid + tt * GRID;     // tile id in [0,1024)
        const int b  = bk >> 7;

        __syncthreads();                    // guard shared reuse across tiles

        // ---- init hash + load per-cell params ----
        #pragma unroll
        for (int i = t; i < HSZ; i += NP) tab[i] = 0xFFFFFFFFu;
        if (t < CC) {
            int base = (bk * CC + t) * 2;
            float m0 = means[base], m1 = means[base + 1];
            float v0 = sqrtf(1.0f / (1e-6f + sigmas[base]))     * SQRT_HALF_LOG2E;
            float v1 = sqrtf(1.0f / (1e-6f + sigmas[base + 1])) * SQRT_HALF_LOG2E;
            sm0[t] = m0;
            sm1[t] = m1;
            scell[t].x = pk2(v0, v1);
            scell[t].y = pk2(-m0 * v0, -m1 * v1);
            sval[t] = values[bk * CC + t];
        }
        __syncthreads();

        // ---- generate integer tuple: cell c = t/12, slot j ----
        int id;
        {
            const int c = t / PPC;
            const int j = t - c * PPC;
            const float m0v = sm0[c], m1v = sm1[c];
            const float SCL = 1.0f - 1e-6f;
            int i0, i1;
            if (j < 4) {
                // fm order (itertools.product([T,F],2)): True->floor
                i0 = (j & 2) ? (int)ceilf(m0v) : (int)floorf(m0v);
                i1 = (j & 1) ? (int)ceilf(m1v) : (int)floorf(m1v);
            } else if (j < 8) {
                int idx = ((bk * CC + c) * GG + (j - 4)) * 2;
                i0 = (int)floorf(__fmul_rn(__fmul_rn(su[idx],     SCL), 1024.0f));
                i1 = (int)floorf(__fmul_rn(__fmul_rn(su[idx + 1], SCL), 1024.0f));
            } else {
                int idx = ((bk * CC + c) * RADR + (j - 8)) * 2;
                float mn0 = rintf(m0v), mn1 = rintf(m1v);   // round half-even
                float lo0 = mn0 - 8.0f, lo1 = mn1 - 8.0f;
                if (lo0 < 0.0f) lo0 = 0.0f;
                if (mn0 + 8.0f > 1024.0f) lo0 = 1008.0f;
                if (lo1 < 0.0f) lo1 = 0.0f;
                if (mn1 + 8.0f > 1024.0f) lo1 = 1008.0f;
                i0 = (int)floorf(__fadd_rn(__fmul_rn(__fmul_rn(ru[idx],     SCL), 16.0f), lo0));
                i1 = (int)floorf(__fadd_rn(__fmul_rn(__fmul_rn(ru[idx + 1], SCL), 16.0f), lo1));
            }
            id = (i0 << 10) | i1;
        }

        // ---- duplicate marking via shared hash (min thread index wins) ----
        bool dup;
        {
            const unsigned int uid = (unsigned int)id;
            const unsigned int val = (uid << 9) | (unsigned int)t;
            unsigned int h = (uid * 2654435761u) >> 23;          // top 9 bits
            int slot;
            for (;;) {
                unsigned int old = atomicCAS(&tab[h], 0xFFFFFFFFu, val);
                if (old == 0xFFFFFFFFu) { slot = h; break; }
                if ((old >> 9) == uid)  { atomicMin(&tab[h], val); slot = h; break; }
                h = (h + 1) & (HSZ - 1);
            }
            __syncthreads();
            dup = ((tab[slot] & 511u) != (unsigned int)t);
            // dup -> p0 = 1e30 => d^2 -> inf => s = -inf => ex2 = exact 0
            spts[t] = pk2(dup ? 1e30f : (float)(id >> 10), (float)(id & 1023));
        }
        __syncthreads();

        // ---- pass 1: warp w owns its 32 points, lane = cell. f32x2 packed ----
        {
            const ulonglong2 cp = scell[l];     // LDS.128
            float c0 = 0.0f, c1 = 0.0f;
            #pragma unroll
            for (int ii = 0; ii < 32; ii += 2) {
                ull pa = spts[(w << 5) + ii];
                ull pb = spts[(w << 5) + ii + 1];
                ull da = fma2(pa, cp.x, cp.y);  // (d0,d1) both dims, 1 slot
                ull db = fma2(pb, cp.x, cp.y);
                ull qa = mul2(da, da);          // (d0^2,d1^2), 1 slot
                ull qb = mul2(db, db);
                float qa0, qa1, qb0, qb1;
                upk2(qa, qa0, qa1);             // reg-pair alias, ~free
                upk2(qb, qb0, qb1);
                c0 += ex2_approx(-qa0 - qa1);   // FADD with neg modifiers
                c1 += ex2_approx(-qb0 - qb1);
            }
            spart[w * CC + l] = c0 + c1;
        }
        __syncthreads();

        // ---- column totals -> value/colsum weights ----
        if (t < CC) {
            float s = 0.0f;
            #pragma unroll
            for (int ww = 0; ww < NWARP; ++ww) s += spart[ww * CC + t];
            svalw[t] = sval[t] / s;
        }
        __syncthreads();

        // ---- pass 2: thread t owns point t; sum over 32 cells, scatter ----
        {
            const ull pp = pk2((float)((id >> 10) & 1023), (float)(id & 1023));
            float a0 = 0.0f, a1 = 0.0f;
            const float2* swv = (const float2*)svalw;
            #pragma unroll
            for (int c = 0; c < CC; c += 2) {
                ulonglong2 ca = scell[c];       // LDS.128
                ulonglong2 cb = scell[c + 1];
                float2 sw = swv[c >> 1];        // LDS.64
                ull da = fma2(pp, ca.x, ca.y);
                ull db = fma2(pp, cb.x, cb.y);
                ull qa = mul2(da, da);
                ull qb = mul2(db, db);
                float qa0, qa1, qb0, qb1;
                upk2(qa, qa0, qa1);
                upk2(qb, qb0, qb1);
                a0 = __fmaf_rn(ex2_approx(-qa0 - qa1), sw.x, a0);
                a1 = __fmaf_rn(ex2_approx(-qb0 - qb1), sw.y, a1);
            }
            if (!dup) {
                float contrib = (a0 + a1) * x[b * INSZ + (id & 1023)];
                atomicAdd(&out[b * OUTSZ + ((id >> 10) & 1023)], contrib);
            }
        }
    }
}

extern "C" void kernel_launch(void* const* d_in, const int* in_sizes, int n_in,
                              void* d_out, int out_size)
{
    const float* x      = (const float*)d_in[0];
    const float* means  = (const float*)d_in[1];
    const float* sigmas = (const float*)d_in[2];
    const float* values = (const float*)d_in[3];
    const float* su     = (const float*)d_in[4];
    const float* ru     = (const float*)d_in[5];
    float* out = (float*)d_out;

    cudaMemsetAsync(out, 0, (size_t)out_size * sizeof(float));
    sparse_layer_kernel<<<GRID, NP>>>(x, means, sigmas, values, su, ru, out);
}

// round 10
// speedup vs baseline: 1.3101x; 1.0109x over previous
#include <cuda_runtime.h>
#include <math.h>

// Fixed problem shapes: b=8, n=4096, c=32, g=4, rad=4, rank=2, k=128, in=1024, OUT=1024
#define BB    8
#define CC    32
#define GG    4
#define RADR  4
#define KK    128
#define PPC   12          // 4 neighbor + 4 sampled + 4 range-restricted
#define NP    384         // CC * PPC points per (b,k) tile
#define INSZ  1024
#define OUTSZ 1024
#define NWARP 12          // NP/32
#define HSZ   512         // dup-hash slots (384 keys @ 75% load)

// sqrt(0.5 * log2(e)) — folds the -0.5 and exp->exp2 into the inverse sigmas.
#define SQRT_HALF_LOG2E 0.8493218383f

__device__ __forceinline__ float ex2_approx(float v) {
    float r;
    asm("ex2.approx.f32 %0, %1;" : "=f"(r) : "f"(v));
    return r;
}

__global__ __launch_bounds__(NP) void sparse_layer_kernel(
    const float* __restrict__ x,        // (8, 1024)
    const float* __restrict__ means,    // (8, 4096, 2)
    const float* __restrict__ sigmas,   // (8, 4096, 2)
    const float* __restrict__ values,   // (8, 4096)
    const float* __restrict__ su,       // (8, 128, 32, 4, 2)
    const float* __restrict__ ru,       // (8, 128, 32, 4, 2)
    float* __restrict__ out)            // (8, 1024)
{
    __shared__ float  sm0[CC], sm1[CC];
    __shared__ float4 scell[CC];            // (v0, v1, m0*v0, m1*v1)
    __shared__ float  sval[CC], svalw[CC];
    __shared__ float2 spts[NP];             // (p0 or 1e30 if dup, p1)
    __shared__ float  spart[NWARP * CC];
    __shared__ unsigned int tab[HSZ];       // hash: (id<<9)|ord, EMPTY=~0

    const int bk = blockIdx.x;              // b*128 + k
    const int b  = bk >> 7;
    const int t  = threadIdx.x;
    const int w  = t >> 5;
    const int l  = t & 31;

    // ---- init hash + load per-cell params ----
    #pragma unroll
    for (int i = t; i < HSZ; i += NP) tab[i] = 0xFFFFFFFFu;
    if (t < CC) {
        int base = (bk * CC + t) * 2;
        float m0 = means[base], m1 = means[base + 1];
        float v0 = sqrtf(1.0f / (1e-6f + sigmas[base]))     * SQRT_HALF_LOG2E;
        float v1 = sqrtf(1.0f / (1e-6f + sigmas[base + 1])) * SQRT_HALF_LOG2E;
        sm0[t] = m0;
        sm1[t] = m1;
        scell[t] = make_float4(v0, v1, m0 * v0, m1 * v1);
        sval[t] = values[bk * CC + t];
    }
    __syncthreads();

    // ---- tuple generation, SLOT-MAJOR: warp w = slot j, lane = cell c ----
    // Each warp is branch-uniform: warps 0-3 neighbor, 4-7 sampled, 8-11 rr.
    const int j = w;                        // slot in [0,12)
    const int c = l;                        // cell in [0,32)
    int id;
    {
        const float m0v = sm0[c], m1v = sm1[c];
        const float SCL = 1.0f - 1e-6f;
        int i0, i1;
        if (j < 4) {
            // fm order (itertools.product([T,F],2)): True->floor
            i0 = (j & 2) ? (int)ceilf(m0v) : (int)floorf(m0v);
            i1 = (j & 1) ? (int)ceilf(m1v) : (int)floorf(m1v);
        } else if (j < 8) {
            int idx = ((bk * CC + c) * GG + (j - 4)) * 2;
            i0 = (int)floorf(__fmul_rn(__fmul_rn(su[idx],     SCL), 1024.0f));
            i1 = (int)floorf(__fmul_rn(__fmul_rn(su[idx + 1], SCL), 1024.0f));
        } else {
            int idx = ((bk * CC + c) * RADR + (j - 8)) * 2;
            float mn0 = rintf(m0v), mn1 = rintf(m1v);   // round half-even (jnp.round)
            float lo0 = mn0 - 8.0f, lo1 = mn1 - 8.0f;
            if (lo0 < 0.0f) lo0 = 0.0f;
            if (mn0 + 8.0f > 1024.0f) lo0 = 1008.0f;
            if (lo1 < 0.0f) lo1 = 0.0f;
            if (mn1 + 8.0f > 1024.0f) lo1 = 1008.0f;
            i0 = (int)floorf(__fadd_rn(__fmul_rn(__fmul_rn(ru[idx],     SCL), 16.0f), lo0));
            i1 = (int)floorf(__fadd_rn(__fmul_rn(__fmul_rn(ru[idx + 1], SCL), 16.0f), lo1));
        }
        id = (i0 << 10) | i1;
    }

    // ---- duplicate marking via shared hash ----
    // Tiebreak on the REFERENCE point order ord = c*12 + j (stable-argsort
    // semantics: first occurrence in reference order wins), independent of
    // our slot-major thread mapping.
    bool dup;
    {
        const unsigned int ord = (unsigned int)(c * PPC + j);    // < 384, 9 bits
        const unsigned int uid = (unsigned int)id;
        const unsigned int val = (uid << 9) | ord;
        unsigned int h = (uid * 2654435761u) >> 23;              // top 9 bits
        int slot;
        for (;;) {
            unsigned int old = atomicCAS(&tab[h], 0xFFFFFFFFu, val);
            if (old == 0xFFFFFFFFu) { slot = h; break; }
            if ((old >> 9) == uid)  { atomicMin(&tab[h], val); slot = h; break; }
            h = (h + 1) & (HSZ - 1);
        }
        __syncthreads();
        dup = ((tab[slot] & 511u) != ord);
        // dup -> p0 = 1e30 => ex2 arg -> -inf => density exactly 0
        spts[t] = make_float2(dup ? 1e30f : (float)(id >> 10), (float)(id & 1023));
    }
    __syncthreads();

    // ---- pass 1: per-cell colsum partials. warp w owns its 32 points, lane = cell ----
    {
        const float4 cp = scell[l];
        float c0 = 0.0f, c1 = 0.0f, c2 = 0.0f, c3 = 0.0f;   // 4-way MUFU-latency split
        #pragma unroll
        for (int ii = 0; ii < 32; ii += 4) {
            float2 pa = spts[(w << 5) + ii];
            float2 pb = spts[(w << 5) + ii + 1];
            float2 pc = spts[(w << 5) + ii + 2];
            float2 pd = spts[(w << 5) + ii + 3];
            float a0 = __fmaf_rn(pa.x, cp.x, -cp.z), a1 = __fmaf_rn(pa.y, cp.y, -cp.w);
            float b0 = __fmaf_rn(pb.x, cp.x, -cp.z), b1 = __fmaf_rn(pb.y, cp.y, -cp.w);
            float d0 = __fmaf_rn(pc.x, cp.x, -cp.z), d1 = __fmaf_rn(pc.y, cp.y, -cp.w);
            float e0 = __fmaf_rn(pd.x, cp.x, -cp.z), e1 = __fmaf_rn(pd.y, cp.y, -cp.w);
            c0 += ex2_approx(__fmaf_rn(-a1, a1, __fmul_rn(-a0, a0)));
            c1 += ex2_approx(__fmaf_rn(-b1, b1, __fmul_rn(-b0, b0)));
            c2 += ex2_approx(__fmaf_rn(-d1, d1, __fmul_rn(-d0, d0)));
            c3 += ex2_approx(__fmaf_rn(-e1, e1, __fmul_rn(-e0, e0)));
        }
        spart[w * CC + l] = (c0 + c1) + (c2 + c3);
    }
    __syncthreads();

    // ---- column totals -> value/colsum weights ----
    if (t < CC) {
        float s = 0.0f;
        #pragma unroll
        for (int ww = 0; ww < NWARP; ++ww) s += spart[ww * CC + t];
        svalw[t] = sval[t] / s;
    }
    __syncthreads();

    // ---- pass 2: thread t owns its point; sum over 32 cells, scatter ----
    {
        const float px = (float)((id >> 10) & 1023);
        const float py = (float)(id & 1023);
        float a0 = 0.0f, a1 = 0.0f;
        const float2* swv = (const float2*)svalw;
        #pragma unroll
        for (int cc2 = 0; cc2 < CC; cc2 += 2) {
            float4 ca = scell[cc2];                 // LDS.128 broadcast
            float4 cb = scell[cc2 + 1];
            float2 sw = swv[cc2 >> 1];              // LDS.64
            float d0 = __fmaf_rn(px, ca.x, -ca.z);
            float d1 = __fmaf_rn(py, ca.y, -ca.w);
            float e0 = __fmaf_rn(px, cb.x, -cb.z);
            float e1 = __fmaf_rn(py, cb.y, -cb.w);
            float wa = ex2_approx(__fmaf_rn(-d1, d1, __fmul_rn(-d0, d0)));
            float wb = ex2_approx(__fmaf_rn(-e1, e1, __fmul_rn(-e0, e0)));
            a0 = __fmaf_rn(wa, sw.x, a0);
            a1 = __fmaf_rn(wb, sw.y, a1);
        }
        if (!dup) {
            float contrib = (a0 + a1) * x[b * INSZ + (id & 1023)];
            atomicAdd(&out[b * OUTSZ + ((id >> 10) & 1023)], contrib);
        }
    }
}

extern "C" void kernel_launch(void* const* d_in, const int* in_sizes, int n_in,
                              void* d_out, int out_size)
{
    const float* x      = (const float*)d_in[0];
    const float* means  = (const float*)d_in[1];
    const float* sigmas = (const float*)d_in[2];
    const float* values = (const float*)d_in[3];
    const float* su     = (const float*)d_in[4];
    const float* ru     = (const float*)d_in[5];
    float* out = (float*)d_out;

    cudaMemsetAsync(out, 0, (size_t)out_size * sizeof(float));
    sparse_layer_kernel<<<BB * KK, NP>>>(x, means, sigmas, values, su, ru, out);
}

// round 12
// speedup vs baseline: 1.8354x; 1.4009x over previous
#include <cuda_runtime.h>
#include <math.h>

// Fixed problem shapes: b=8, n=4096, c=32, g=4, rad=4, rank=2, k=128, in=1024, OUT=1024
#define BB    8
#define CC    32
#define GG    4
#define RADR  4
#define KK    128
#define PPC   12          // 4 neighbor + 4 sampled + 4 range-restricted
#define NP    384         // CC * PPC points per (b,k) tile
#define INSZ  1024
#define OUTSZ 1024
#define NWARP 12          // NP/32
#define HSZ   1024        // dup-hash slots. 384/1024 = 0.375 load -> ~1.8 probes.
                          // HSZ=512 (0.75 load, ~8.5 probes) measured +8us: R8/R9/R10.

// sqrt(0.5 * log2(e)) — folds the -0.5 and exp->exp2 into the inverse sigmas.
#define SQRT_HALF_LOG2E 0.8493218383f

__device__ __forceinline__ float ex2_approx(float v) {
    float r;
    asm("ex2.approx.f32 %0, %1;" : "=f"(r) : "f"(v));
    return r;
}

__global__ __launch_bounds__(NP) void sparse_layer_kernel(
    const float* __restrict__ x,        // (8, 1024)
    const float* __restrict__ means,    // (8, 4096, 2)
    const float* __restrict__ sigmas,   // (8, 4096, 2)
    const float* __restrict__ values,   // (8, 4096)
    const float* __restrict__ su,       // (8, 128, 32, 4, 2)
    const float* __restrict__ ru,       // (8, 128, 32, 4, 2)
    float* __restrict__ out)            // (8, 1024)
{
    __shared__ float  sm0[CC], sm1[CC];
    __shared__ float4 scell[CC];            // (v0, v1, m0*v0, m1*v1)
    __shared__ float  sval[CC], svalw[CC];
    __shared__ float2 spts[NP];             // (p0 or 1e30 if dup, p1)
    __shared__ float  spart[NWARP * CC];
    __shared__ unsigned int tab[HSZ];       // hash: (id<<9)|ord, EMPTY=~0

    const int bk = blockIdx.x;              // b*128 + k
    const int b  = bk >> 7;
    const int t  = threadIdx.x;
    const int w  = t >> 5;
    const int l  = t & 31;

    // ---- init hash + load per-cell params ----
    #pragma unroll
    for (int i = t; i < HSZ; i += NP) tab[i] = 0xFFFFFFFFu;
    if (t < CC) {
        int base = (bk * CC + t) * 2;
        float m0 = means[base], m1 = means[base + 1];
        float v0 = sqrtf(1.0f / (1e-6f + sigmas[base]))     * SQRT_HALF_LOG2E;
        float v1 = sqrtf(1.0f / (1e-6f + sigmas[base + 1])) * SQRT_HALF_LOG2E;
        sm0[t] = m0;
        sm1[t] = m1;
        scell[t] = make_float4(v0, v1, m0 * v0, m1 * v1);
        sval[t] = values[bk * CC + t];
    }
    __syncthreads();

    // ---- tuple generation, SLOT-MAJOR: warp w = slot j, lane = cell c ----
    // Each warp is branch-uniform: warps 0-3 neighbor, 4-7 sampled, 8-11 rr.
    const int j = w;                        // slot in [0,12)
    const int c = l;                        // cell in [0,32)
    int id;
    {
        const float m0v = sm0[c], m1v = sm1[c];
        const float SCL = 1.0f - 1e-6f;
        int i0, i1;
        if (j < 4) {
            // fm order (itertools.product([T,F],2)): True->floor
            i0 = (j & 2) ? (int)ceilf(m0v) : (int)floorf(m0v);
            i1 = (j & 1) ? (int)ceilf(m1v) : (int)floorf(m1v);
        } else if (j < 8) {
            int idx = ((bk * CC + c) * GG + (j - 4)) * 2;
            i0 = (int)floorf(__fmul_rn(__fmul_rn(su[idx],     SCL), 1024.0f));
            i1 = (int)floorf(__fmul_rn(__fmul_rn(su[idx + 1], SCL), 1024.0f));
        } else {
            int idx = ((bk * CC + c) * RADR + (j - 8)) * 2;
            float mn0 = rintf(m0v), mn1 = rintf(m1v);   // round half-even (jnp.round)
            float lo0 = mn0 - 8.0f, lo1 = mn1 - 8.0f;
            if (lo0 < 0.0f) lo0 = 0.0f;
            if (mn0 + 8.0f > 1024.0f) lo0 = 1008.0f;
            if (lo1 < 0.0f) lo1 = 0.0f;
            if (mn1 + 8.0f > 1024.0f) lo1 = 1008.0f;
            i0 = (int)floorf(__fadd_rn(__fmul_rn(__fmul_rn(ru[idx],     SCL), 16.0f), lo0));
            i1 = (int)floorf(__fadd_rn(__fmul_rn(__fmul_rn(ru[idx + 1], SCL), 16.0f), lo1));
        }
        id = (i0 << 10) | i1;
    }

    // ---- duplicate marking via shared hash ----
    // Tiebreak on the REFERENCE point order ord = c*12 + j (stable-argsort
    // semantics: first occurrence in reference order wins), independent of
    // our slot-major thread mapping.
    bool dup;
    {
        const unsigned int ord = (unsigned int)(c * PPC + j);    // < 384, 9 bits
        const unsigned int uid = (unsigned int)id;
        const unsigned int val = (uid << 9) | ord;
        unsigned int h = (uid * 2654435761u) >> 22;              // top 10 bits
        int slot;
        for (;;) {
            unsigned int old = atomicCAS(&tab[h], 0xFFFFFFFFu, val);
            if (old == 0xFFFFFFFFu) { slot = h; break; }
            if ((old >> 9) == uid)  { atomicMin(&tab[h], val); slot = h; break; }
            h = (h + 1) & (HSZ - 1);
        }
        __syncthreads();
        dup = ((tab[slot] & 511u) != ord);
        // dup -> p0 = 1e30 => ex2 arg -> -inf => density exactly 0
        spts[t] = make_float2(dup ? 1e30f : (float)(id >> 10), (float)(id & 1023));
    }
    __syncthreads();

    // ---- pass 1: per-cell colsum partials. warp w owns its 32 points, lane = cell ----
    {
        const float4 cp = scell[l];
        float c0 = 0.0f, c1 = 0.0f, c2 = 0.0f, c3 = 0.0f;   // 4-way MUFU-latency split
        #pragma unroll
        for (int ii = 0; ii < 32; ii += 4) {
            float2 pa = spts[(w << 5) + ii];
            float2 pb = spts[(w << 5) + ii + 1];
            float2 pc = spts[(w << 5) + ii + 2];
            float2 pd = spts[(w << 5) + ii + 3];
            float a0 = __fmaf_rn(pa.x, cp.x, -cp.z), a1 = __fmaf_rn(pa.y, cp.y, -cp.w);
            float b0 = __fmaf_rn(pb.x, cp.x, -cp.z), b1 = __fmaf_rn(pb.y, cp.y, -cp.w);
            float d0 = __fmaf_rn(pc.x, cp.x, -cp.z), d1 = __fmaf_rn(pc.y, cp.y, -cp.w);
            float e0 = __fmaf_rn(pd.x, cp.x, -cp.z), e1 = __fmaf_rn(pd.y, cp.y, -cp.w);
            c0 += ex2_approx(__fmaf_rn(-a1, a1, __fmul_rn(-a0, a0)));
            c1 += ex2_approx(__fmaf_rn(-b1, b1, __fmul_rn(-b0, b0)));
            c2 += ex2_approx(__fmaf_rn(-d1, d1, __fmul_rn(-d0, d0)));
            c3 += ex2_approx(__fmaf_rn(-e1, e1, __fmul_rn(-e0, e0)));
        }
        spart[w * CC + l] = (c0 + c1) + (c2 + c3);
    }
    __syncthreads();

    // ---- column totals -> value/colsum weights ----
    if (t < CC) {
        float s = 0.0f;
        #pragma unroll
        for (int ww = 0; ww < NWARP; ++ww) s += spart[ww * CC + t];
        svalw[t] = sval[t] / s;
    }
    __syncthreads();

    // ---- pass 2: thread t owns its point; sum over 32 cells, scatter ----
    {
        const float px = (float)((id >> 10) & 1023);
        const float py = (float)(id & 1023);
        float a0 = 0.0f, a1 = 0.0f;
        const float2* swv = (const float2*)svalw;
        #pragma unroll
        for (int cc2 = 0; cc2 < CC; cc2 += 2) {
            float4 ca = scell[cc2];                 // LDS.128 broadcast
            float4 cb = scell[cc2 + 1];
            float2 sw = swv[cc2 >> 1];              // LDS.64
            float d0 = __fmaf_rn(px, ca.x, -ca.z);
            float d1 = __fmaf_rn(py, ca.y, -ca.w);
            float e0 = __fmaf_rn(px, cb.x, -cb.z);
            float e1 = __fmaf_rn(py, cb.y, -cb.w);
            float wa = ex2_approx(__fmaf_rn(-d1, d1, __fmul_rn(-d0, d0)));
            float wb = ex2_approx(__fmaf_rn(-e1, e1, __fmul_rn(-e0, e0)));
            a0 = __fmaf_rn(wa, sw.x, a0);
            a1 = __fmaf_rn(wb, sw.y, a1);
        }
        if (!dup) {
            float contrib = (a0 + a1) * x[b * INSZ + (id & 1023)];
            atomicAdd(&out[b * OUTSZ + ((id >> 10) & 1023)], contrib);
        }
    }
}

extern "C" void kernel_launch(void* const* d_in, const int* in_sizes, int n_in,
                              void* d_out, int out_size)
{
    const float* x      = (const float*)d_in[0];
    const float* means  = (const float*)d_in[1];
    const float* sigmas = (const float*)d_in[2];
    const float* values = (const float*)d_in[3];
    const float* su     = (const float*)d_in[4];
    const float* ru     = (const float*)d_in[5];
    float* out = (float*)d_out;

    cudaMemsetAsync(out, 0, (size_t)out_size * sizeof(float));
    sparse_layer_kernel<<<BB * KK, NP>>>(x, means, sigmas, values, su, ru, out);
}